// round 2
// baseline (speedup 1.0000x reference)
#include <cuda_runtime.h>

// CoverageAttention on GB300 — Round 1 baseline: exact fp32 SIMT.
// B=8, Tq=Tk=1024, d_model=1024, H=16, hd=64, SCALE=8.

#define NB   8
#define NH   16
#define NT   1024
#define NDM  1024
#define NHD  64

// ---------------- scratch (static device globals; no allocation) ----------------
__device__ float g_Q[NB * NH * NT * NHD];       // [b,h,t,d]
__device__ float g_K[NB * NH * NT * NHD];
__device__ float g_V[NB * NH * NT * NHD];
__device__ float g_O[NB * NT * NDM];            // attn output, [b*t, h*64+d]
__device__ float g_covacc[NB * NT];

__global__ void zero_covacc_kernel() {
    int i = blockIdx.x * 256 + threadIdx.x;
    if (i < NB * NT) g_covacc[i] = 0.0f;
}

// ---------------- GEMM: C[m,n] = sum_k A[m,k] * W[n,k] + bias[n] ----------------
// M=8192, N=1024, K=1024. 128x128 block tile, BK=8, 256 threads, 8x8 per thread
// (split as 2 x float4 fragments at tx*4 and 64+tx*4 for conflict-free LDS).
// DST: 0->g_Q (headed), 1->g_K (headed), 2->g_V (headed), 3->plain to Cout (A=g_O).
template <int DST>
__global__ __launch_bounds__(256, 2) void gemm_kernel(
    const float* __restrict__ A, const float* __restrict__ W,
    const float* __restrict__ bias, float* __restrict__ Cout)
{
    __shared__ float As[8][128];
    __shared__ float Ws[8][128];

    const float* Ap = (DST == 3) ? (const float*)g_O : A;

    int tid = threadIdx.x;
    int tx = tid & 15;
    int ty = tid >> 4;
    int bm = blockIdx.y * 128;
    int bn = blockIdx.x * 128;

    int lr = tid >> 1;            // 0..127: tile row being loaded
    int lc = (tid & 1) << 2;      // 0 or 4: k offset within BK=8

    const float* aP = Ap + (size_t)(bm + lr) * NDM + lc;
    const float* wP = W  + (size_t)(bn + lr) * NDM + lc;

    float acc[8][8];
#pragma unroll
    for (int i = 0; i < 8; i++)
#pragma unroll
        for (int j = 0; j < 8; j++) acc[i][j] = 0.0f;

    for (int k0 = 0; k0 < NDM; k0 += 8) {
        float4 av = *(const float4*)(aP + k0);
        float4 wv = *(const float4*)(wP + k0);
        __syncthreads();
        As[lc + 0][lr] = av.x; As[lc + 1][lr] = av.y;
        As[lc + 2][lr] = av.z; As[lc + 3][lr] = av.w;
        Ws[lc + 0][lr] = wv.x; Ws[lc + 1][lr] = wv.y;
        Ws[lc + 2][lr] = wv.z; Ws[lc + 3][lr] = wv.w;
        __syncthreads();
#pragma unroll
        for (int k = 0; k < 8; k++) {
            float4 a0 = *(const float4*)&As[k][ty * 4];
            float4 a1 = *(const float4*)&As[k][64 + ty * 4];
            float4 w0 = *(const float4*)&Ws[k][tx * 4];
            float4 w1 = *(const float4*)&Ws[k][64 + tx * 4];
            float ar[8] = {a0.x, a0.y, a0.z, a0.w, a1.x, a1.y, a1.z, a1.w};
            float wr[8] = {w0.x, w0.y, w0.z, w0.w, w1.x, w1.y, w1.z, w1.w};
#pragma unroll
            for (int i = 0; i < 8; i++)
#pragma unroll
                for (int j = 0; j < 8; j++)
                    acc[i][j] += ar[i] * wr[j];
        }
    }

#pragma unroll
    for (int i = 0; i < 8; i++) {
        int mloc = (i < 4) ? (ty * 4 + i) : (64 + ty * 4 + (i - 4));
        int m = bm + mloc;
        int bb = m >> 10;
        int t  = m & 1023;
#pragma unroll
        for (int j = 0; j < 8; j++) {
            int nloc = (j < 4) ? (tx * 4 + j) : (64 + tx * 4 + (j - 4));
            int n = bn + nloc;
            float v = acc[i][j] + bias[n];
            if (DST == 0) {
                g_Q[(((size_t)(bb * NH + (n >> 6))) * NT + t) * NHD + (n & 63)] = v;
            } else if (DST == 1) {
                g_K[(((size_t)(bb * NH + (n >> 6))) * NT + t) * NHD + (n & 63)] = v;
            } else if (DST == 2) {
                g_V[(((size_t)(bb * NH + (n >> 6))) * NT + t) * NHD + (n & 63)] = v;
            } else {
                Cout[(size_t)m * NDM + n] = v;
            }
        }
    }
}

// ---------------- attention: one block = (b,h) x 32 q-rows, full fp32 scores ----
#define SROW  1032
#define OFF_S 0                       // 32*1032 = 33024 floats: scores/probs
#define OFF_Q 33024                   // 32*65   =  2080: Q tile
#define OFF_K 35104                   // 64*65   =  4160: K(transposed)/V tile
#define OFF_R 39264                   // 32: 1/l per row
#define OFF_C 39296                   // 1024: coverage*wcov bias
#define SMEM_FLOATS (OFF_C + 1024)    // 40320
#define SMEM_BYTES  (SMEM_FLOATS * 4) // 161280 B

__global__ __launch_bounds__(256, 1) void attn_kernel(
    const float* __restrict__ coverage, const float* __restrict__ Wcov)
{
    extern __shared__ float sm[];
    int tid = threadIdx.x;
    int bh = blockIdx.y;
    int b = bh >> 4;
    int h = bh & 15;
    int q0 = blockIdx.x * 32;
    float wcov = Wcov[h];

    const float* Qb = g_Q + (size_t)bh * NT * NHD;
    const float* Kb = g_K + (size_t)bh * NT * NHD;
    const float* Vb = g_V + (size_t)bh * NT * NHD;

    // load Q tile [32 x 64] (padded rows) and coverage bias
    for (int i = tid; i < 32 * 64; i += 256) {
        int q = i >> 6, d = i & 63;
        sm[OFF_Q + q * 65 + d] = Qb[(size_t)(q0 + q) * NHD + d];
    }
    for (int i = tid; i < NT; i += 256) {
        sm[OFF_C + i] = coverage[b * NT + i] * wcov;
    }

    int tx = tid & 15;     // k / d dimension (4 each)
    int ty = tid >> 4;     // q dimension (2 each)

    // -------- phase 1: scores S[32 x 1024] --------
    for (int kt = 0; kt < 16; kt++) {
        // load K tile transposed: KS[d][k], row stride 65
        for (int i = tid; i < 64 * 64; i += 256) {
            int k = i >> 6, d = i & 63;
            sm[OFF_K + d * 65 + k] = Kb[(size_t)(kt * 64 + k) * NHD + d];
        }
        __syncthreads();

        float acc[2][4];
#pragma unroll
        for (int i = 0; i < 2; i++)
#pragma unroll
            for (int j = 0; j < 4; j++) acc[i][j] = 0.0f;

#pragma unroll 8
        for (int d = 0; d < 64; d++) {
            float a0 = sm[OFF_Q + (ty * 2 + 0) * 65 + d];
            float a1 = sm[OFF_Q + (ty * 2 + 1) * 65 + d];
#pragma unroll
            for (int j = 0; j < 4; j++) {
                float kv = sm[OFF_K + d * 65 + tx * 4 + j];
                acc[0][j] += a0 * kv;
                acc[1][j] += a1 * kv;
            }
        }

        int kg = kt * 64 + tx * 4;
#pragma unroll
        for (int i = 0; i < 2; i++) {
            float4 sv;
            sv.x = acc[i][0] * 0.125f + sm[OFF_C + kg + 0];
            sv.y = acc[i][1] * 0.125f + sm[OFF_C + kg + 1];
            sv.z = acc[i][2] * 0.125f + sm[OFF_C + kg + 2];
            sv.w = acc[i][3] * 0.125f + sm[OFF_C + kg + 3];
            *(float4*)&sm[OFF_S + (ty * 2 + i) * SROW + kg] = sv;
        }
        __syncthreads();
    }

    // -------- phase 2: softmax (warp per row group) --------
    int lane = tid & 31;
    int wrp = tid >> 5;
    for (int q = wrp; q < 32; q += 8) {
        float* row = &sm[OFF_S + q * SROW];
        float m = -1e30f;
        for (int k = lane; k < NT; k += 32) m = fmaxf(m, row[k]);
#pragma unroll
        for (int o = 16; o > 0; o >>= 1) m = fmaxf(m, __shfl_xor_sync(0xffffffff, m, o));
        float l = 0.0f;
        for (int k = lane; k < NT; k += 32) {
            float e = __expf(row[k] - m);
            row[k] = e;
            l += e;
        }
#pragma unroll
        for (int o = 16; o > 0; o >>= 1) l += __shfl_xor_sync(0xffffffff, l, o);
        if (lane == 0) sm[OFF_R + q] = 1.0f / l;
    }
    __syncthreads();

    // -------- phase 3: coverage column sums --------
    for (int k = tid; k < NT; k += 256) {
        float s = 0.0f;
#pragma unroll 8
        for (int q = 0; q < 32; q++)
            s += sm[OFF_S + q * SROW + k] * sm[OFF_R + q];
        atomicAdd(&g_covacc[b * NT + k], s);
    }

    // -------- phase 4: O = P @ V --------
    float oacc[2][4];
#pragma unroll
    for (int i = 0; i < 2; i++)
#pragma unroll
        for (int j = 0; j < 4; j++) oacc[i][j] = 0.0f;

    for (int kt = 0; kt < 16; kt++) {
        __syncthreads();
        // load V tile natural layout VS[k][d], row stride 65
        for (int i = tid; i < 64 * 64; i += 256) {
            int k = i >> 6, d = i & 63;
            sm[OFF_K + k * 65 + d] = Vb[(size_t)(kt * 64 + k) * NHD + d];
        }
        __syncthreads();
#pragma unroll 8
        for (int kk = 0; kk < 64; kk++) {
            float e0 = sm[OFF_S + (ty * 2 + 0) * SROW + kt * 64 + kk];
            float e1 = sm[OFF_S + (ty * 2 + 1) * SROW + kt * 64 + kk];
#pragma unroll
            for (int j = 0; j < 4; j++) {
                float vv = sm[OFF_K + kk * 65 + tx * 4 + j];
                oacc[0][j] += e0 * vv;
                oacc[1][j] += e1 * vv;
            }
        }
    }

#pragma unroll
    for (int i = 0; i < 2; i++) {
        float inv = sm[OFF_R + ty * 2 + i];
        int qg = q0 + ty * 2 + i;
        float4 ov;
        ov.x = oacc[i][0] * inv;
        ov.y = oacc[i][1] * inv;
        ov.z = oacc[i][2] * inv;
        ov.w = oacc[i][3] * inv;
        *(float4*)&g_O[((size_t)(b * NT + qg)) * NDM + h * 64 + tx * 4] = ov;
    }
}

__global__ void finalize_cov_kernel(const float* __restrict__ coverage,
                                    float* __restrict__ outcov)
{
    int i = blockIdx.x * 256 + threadIdx.x;
    if (i < NB * NT) outcov[i] = coverage[i] + g_covacc[i] * (1.0f / NH);
}

// ---------------- launcher ----------------
extern "C" void kernel_launch(void* const* d_in, const int* in_sizes, int n_in,
                              void* d_out, int out_size)
{
    const float* query    = (const float*)d_in[0];
    const float* memory   = (const float*)d_in[1];
    const float* coverage = (const float*)d_in[2];
    const float* Wq       = (const float*)d_in[3];
    const float* bq       = (const float*)d_in[4];
    const float* Wk       = (const float*)d_in[5];
    const float* bk       = (const float*)d_in[6];
    const float* Wv       = (const float*)d_in[7];
    const float* bv       = (const float*)d_in[8];
    const float* Wo       = (const float*)d_in[9];
    const float* bo       = (const float*)d_in[10];
    const float* Wcov     = (const float*)d_in[11];
    float* out = (float*)d_out;

    cudaFuncSetAttribute(attn_kernel,
                         cudaFuncAttributeMaxDynamicSharedMemorySize, SMEM_BYTES);

    zero_covacc_kernel<<<32, 256>>>();

    dim3 gg(NDM / 128, (NB * NT) / 128);   // (8, 64)
    gemm_kernel<0><<<gg, 256>>>(query,  Wq, bq, nullptr);
    gemm_kernel<1><<<gg, 256>>>(memory, Wk, bk, nullptr);
    gemm_kernel<2><<<gg, 256>>>(memory, Wv, bv, nullptr);

    attn_kernel<<<dim3(NT / 32, NB * NH), 256, SMEM_BYTES>>>(coverage, Wcov);

    gemm_kernel<3><<<gg, 256>>>(nullptr, Wo, bo, out);

    finalize_cov_kernel<<<32, 256>>>(coverage, out + (size_t)NB * NT * NDM);
}

// round 4
// speedup vs baseline: 1.3847x; 1.3847x over previous
#include <cuda_runtime.h>
#include <cstdint>

// CoverageAttention GB300 — R3: tf32 mma.sync GEMMs (compute_103-portable) +
// FMA-bound SIMT attention. B=8, Tq=Tk=1024, d_model=1024, H=16, hd=64, SCALE=8.

#define NB   8
#define NH   16
#define NT   1024
#define NDM  1024
#define NHD  64

// ---------------- scratch ----------------
__device__ float g_Q[NB * NH * NT * NHD];
__device__ float g_K[NB * NH * NT * NHD];
__device__ float g_V[NB * NH * NT * NHD];
__device__ float g_O[NB * NT * NDM];
__device__ float g_covacc[NB * NT];

__global__ void zero_covacc_kernel() {
    int i = blockIdx.x * 256 + threadIdx.x;
    if (i < NB * NT) g_covacc[i] = 0.0f;
}

__device__ __forceinline__ uint32_t f2tf32(float x) {
    uint32_t r;
    asm("cvt.rna.tf32.f32 %0, %1;" : "=r"(r) : "f"(x));
    return r;
}

__device__ __forceinline__ void mma_tf32(float c[4],
                                         uint32_t a0, uint32_t a1, uint32_t a2, uint32_t a3,
                                         uint32_t b0, uint32_t b1) {
    asm volatile(
        "mma.sync.aligned.m16n8k8.row.col.f32.tf32.tf32.f32 "
        "{%0,%1,%2,%3}, {%4,%5,%6,%7}, {%8,%9}, {%0,%1,%2,%3};"
        : "+f"(c[0]), "+f"(c[1]), "+f"(c[2]), "+f"(c[3])
        : "r"(a0), "r"(a1), "r"(a2), "r"(a3), "r"(b0), "r"(b1));
}

// ================= tf32 GEMM: C[m,n] = A[m,:]·W[n,:] + bias[n] =================
// M=8192, N=1024, K=1024. CTA tile 128x128, BK=16, 256 threads = 8 warps (2x4).
// Warp tile 64x32 = 4x4 m16n8k8 fragments. Register prefetch of next K slab.
// DST: 0->g_Q (headed), 1->g_K, 2->g_V, 3->plain Cout (A = g_O).
template <int DST>
__global__ __launch_bounds__(256) void gemm_mma(
    const float* __restrict__ A, const float* __restrict__ W,
    const float* __restrict__ bias, float* __restrict__ Cout)
{
    __shared__ uint32_t As[128][20];   // [row][k] tf32 bits, pad 16->20
    __shared__ uint32_t Ws[128][20];

    int tid = threadIdx.x;
    int lane = tid & 31;
    int wid = tid >> 5;
    int warp_m = wid & 1;        // 2 along M
    int warp_n = wid >> 1;       // 4 along N
    int g = lane >> 2;           // 0..7
    int t = lane & 3;            // 0..3

    int bm = blockIdx.y * 128;
    int bn = blockIdx.x * 128;

    const float* Ap = (DST == 3) ? (const float*)g_O : A;

    int lr = tid >> 1;           // 0..127: row loaded by this thread
    int kc = (tid & 1) * 8;      // 0 or 8: k offset within BK=16
    const float* aP = Ap + (size_t)(bm + lr) * NDM + kc;
    const float* wP = W  + (size_t)(bn + lr) * NDM + kc;

    float c[4][4][4];
#pragma unroll
    for (int mi = 0; mi < 4; mi++)
#pragma unroll
        for (int ni = 0; ni < 4; ni++)
#pragma unroll
            for (int e = 0; e < 4; e++) c[mi][ni][e] = 0.0f;

    // prefetch first K slab
    float4 ar0 = *(const float4*)(aP + 0);
    float4 ar1 = *(const float4*)(aP + 4);
    float4 wr0 = *(const float4*)(wP + 0);
    float4 wr1 = *(const float4*)(wP + 4);

    for (int kt = 0; kt < 64; kt++) {
        // store current slab (cvt to tf32)
        As[lr][kc + 0] = f2tf32(ar0.x); As[lr][kc + 1] = f2tf32(ar0.y);
        As[lr][kc + 2] = f2tf32(ar0.z); As[lr][kc + 3] = f2tf32(ar0.w);
        As[lr][kc + 4] = f2tf32(ar1.x); As[lr][kc + 5] = f2tf32(ar1.y);
        As[lr][kc + 6] = f2tf32(ar1.z); As[lr][kc + 7] = f2tf32(ar1.w);
        Ws[lr][kc + 0] = f2tf32(wr0.x); Ws[lr][kc + 1] = f2tf32(wr0.y);
        Ws[lr][kc + 2] = f2tf32(wr0.z); Ws[lr][kc + 3] = f2tf32(wr0.w);
        Ws[lr][kc + 4] = f2tf32(wr1.x); Ws[lr][kc + 5] = f2tf32(wr1.y);
        Ws[lr][kc + 6] = f2tf32(wr1.z); Ws[lr][kc + 7] = f2tf32(wr1.w);
        __syncthreads();

        if (kt < 63) {
            const float* aN = aP + (kt + 1) * 16;
            const float* wN = wP + (kt + 1) * 16;
            ar0 = *(const float4*)(aN + 0);
            ar1 = *(const float4*)(aN + 4);
            wr0 = *(const float4*)(wN + 0);
            wr1 = *(const float4*)(wN + 4);
        }

#pragma unroll
        for (int kk = 0; kk < 16; kk += 8) {
            uint32_t af[4][4];
#pragma unroll
            for (int mi = 0; mi < 4; mi++) {
                int r0 = warp_m * 64 + mi * 16 + g;
                af[mi][0] = As[r0][kk + t];
                af[mi][1] = As[r0 + 8][kk + t];
                af[mi][2] = As[r0][kk + t + 4];
                af[mi][3] = As[r0 + 8][kk + t + 4];
            }
            uint32_t bf[4][2];
#pragma unroll
            for (int ni = 0; ni < 4; ni++) {
                int c0 = warp_n * 32 + ni * 8 + g;
                bf[ni][0] = Ws[c0][kk + t];
                bf[ni][1] = Ws[c0][kk + t + 4];
            }
#pragma unroll
            for (int mi = 0; mi < 4; mi++)
#pragma unroll
                for (int ni = 0; ni < 4; ni++)
                    mma_tf32(c[mi][ni], af[mi][0], af[mi][1], af[mi][2], af[mi][3],
                             bf[ni][0], bf[ni][1]);
        }
        __syncthreads();
    }

    // epilogue: fragment scatter + bias
#pragma unroll
    for (int mi = 0; mi < 4; mi++) {
#pragma unroll
        for (int ni = 0; ni < 4; ni++) {
            int n0 = bn + warp_n * 32 + ni * 8 + t * 2;
            float b0v = __ldg(bias + n0);
            float b1v = __ldg(bias + n0 + 1);
#pragma unroll
            for (int rh = 0; rh < 2; rh++) {
                int m = bm + warp_m * 64 + mi * 16 + g + rh * 8;
                float v0 = c[mi][ni][rh * 2 + 0] + b0v;
                float v1 = c[mi][ni][rh * 2 + 1] + b1v;
                int bb = m >> 10, tok = m & 1023;
                if (DST == 0) {
                    size_t base = (((size_t)(bb * NH + (n0 >> 6))) * NT + tok) * NHD + (n0 & 63);
                    g_Q[base] = v0; g_Q[base + 1] = v1;
                } else if (DST == 1) {
                    size_t base = (((size_t)(bb * NH + (n0 >> 6))) * NT + tok) * NHD + (n0 & 63);
                    g_K[base] = v0; g_K[base + 1] = v1;
                } else if (DST == 2) {
                    size_t base = (((size_t)(bb * NH + (n0 >> 6))) * NT + tok) * NHD + (n0 & 63);
                    g_V[base] = v0; g_V[base + 1] = v1;
                } else {
                    Cout[(size_t)m * NDM + n0] = v0;
                    Cout[(size_t)m * NDM + n0 + 1] = v1;
                }
            }
        }
    }
}

// ================= attention =================
// One block = (b,h) x 32 q rows. 256 threads. Exact fp32.
#define SROW   1033
#define OFF_S  0
#define OFF_T  33056
#define OFF_Q  OFF_T
#define OFF_K  (OFF_T + 2080)
#define OFF_R  51776
#define OFF_C  51808
#define A_SMEM_FLOATS 52832
#define A_SMEM_BYTES  (A_SMEM_FLOATS * 4)   // 211328

__global__ __launch_bounds__(256) void attn_kernel(
    const float* __restrict__ coverage, const float* __restrict__ Wcov)
{
    extern __shared__ float sm[];
    int tid = threadIdx.x;
    int bh = blockIdx.y;
    int b = bh >> 4;
    int h = bh & 15;
    int q0 = blockIdx.x * 32;
    float wcov = Wcov[h];

    const float* Qb = g_Q + (size_t)bh * NT * NHD;
    const float* Kb = g_K + (size_t)bh * NT * NHD;
    const float* Vb = g_V + (size_t)bh * NT * NHD;

    for (int i = tid; i < 32 * 64; i += 256) {
        int q = i >> 6, d = i & 63;
        sm[OFF_Q + q * 65 + d] = Qb[(size_t)(q0 + q) * NHD + d];
    }
    for (int i = tid; i < NT; i += 256)
        sm[OFF_C + i] = coverage[b * NT + i] * wcov;

    // -------- phase 1: S[32 x 1024], 4q x 8k per thread (k = tx + 32j) --------
    {
        int tx = tid & 31;
        int ty4 = (tid >> 5) * 4;
        for (int kt = 0; kt < 4; kt++) {
            int kbase = kt * 256;
            for (int i = tid; i < 256 * 64; i += 256) {
                int k = i >> 6, d = i & 63;
                sm[OFF_K + k * 65 + d] = Kb[(size_t)(kbase + k) * NHD + d];
            }
            __syncthreads();

            float acc[4][8];
#pragma unroll
            for (int i = 0; i < 4; i++)
#pragma unroll
                for (int j = 0; j < 8; j++) acc[i][j] = 0.0f;

#pragma unroll 2
            for (int d = 0; d < 64; d++) {
                float q0v = sm[OFF_Q + (ty4 + 0) * 65 + d];
                float q1v = sm[OFF_Q + (ty4 + 1) * 65 + d];
                float q2v = sm[OFF_Q + (ty4 + 2) * 65 + d];
                float q3v = sm[OFF_Q + (ty4 + 3) * 65 + d];
#pragma unroll
                for (int j = 0; j < 8; j++) {
                    float kv = sm[OFF_K + (tx + 32 * j) * 65 + d];
                    acc[0][j] += q0v * kv;
                    acc[1][j] += q1v * kv;
                    acc[2][j] += q2v * kv;
                    acc[3][j] += q3v * kv;
                }
            }
#pragma unroll
            for (int i = 0; i < 4; i++)
#pragma unroll
                for (int j = 0; j < 8; j++) {
                    int kg = kbase + tx + 32 * j;
                    sm[OFF_S + (ty4 + i) * SROW + kg] = acc[i][j] * 0.125f + sm[OFF_C + kg];
                }
            __syncthreads();
        }
    }

    // -------- phase 2: softmax --------
    {
        int lane = tid & 31;
        int wrp = tid >> 5;
        for (int q = wrp; q < 32; q += 8) {
            float* row = &sm[OFF_S + q * SROW];
            float m = -1e30f;
            for (int k = lane; k < NT; k += 32) m = fmaxf(m, row[k]);
#pragma unroll
            for (int o = 16; o > 0; o >>= 1) m = fmaxf(m, __shfl_xor_sync(0xffffffff, m, o));
            float l = 0.0f;
            for (int k = lane; k < NT; k += 32) {
                float e = __expf(row[k] - m);
                row[k] = e;
                l += e;
            }
#pragma unroll
            for (int o = 16; o > 0; o >>= 1) l += __shfl_xor_sync(0xffffffff, l, o);
            if (lane == 0) sm[OFF_R + q] = 1.0f / l;
        }
        __syncthreads();
    }

    // -------- phase 3: coverage column sums --------
    for (int k = tid; k < NT; k += 256) {
        float s = 0.0f;
#pragma unroll 8
        for (int q = 0; q < 32; q++)
            s += sm[OFF_S + q * SROW + k] * sm[OFF_R + q];
        atomicAdd(&g_covacc[b * NT + k], s);
    }

    // -------- phase 4: O = P @ V, split-k into 4 groups of 64 threads --------
    {
        int grp = tid >> 6;
        int tyq4 = ((tid >> 3) & 7) * 4;
        int txd8 = (tid & 7) * 8;

        float oacc[4][8];
#pragma unroll
        for (int i = 0; i < 4; i++)
#pragma unroll
            for (int j = 0; j < 8; j++) oacc[i][j] = 0.0f;

        for (int t = 0; t < 4; t++) {
            __syncthreads();
            for (int i = tid; i < 4 * 64 * 64; i += 256) {
                int g2 = i >> 12;
                int kk = (i >> 6) & 63;
                int d = i & 63;
                sm[OFF_T + (g2 * 64 + kk) * 68 + d] =
                    Vb[(size_t)(g2 * 256 + t * 64 + kk) * NHD + d];
            }
            __syncthreads();
            int kb = grp * 256 + t * 64;
#pragma unroll 2
            for (int kk = 0; kk < 64; kk++) {
                float p0 = sm[OFF_S + (tyq4 + 0) * SROW + kb + kk];
                float p1 = sm[OFF_S + (tyq4 + 1) * SROW + kb + kk];
                float p2 = sm[OFF_S + (tyq4 + 2) * SROW + kb + kk];
                float p3 = sm[OFF_S + (tyq4 + 3) * SROW + kb + kk];
                const float* Vr = &sm[OFF_T + (grp * 64 + kk) * 68 + txd8];
                float4 v0 = *(const float4*)Vr;
                float4 v1 = *(const float4*)(Vr + 4);
                float vv[8] = {v0.x, v0.y, v0.z, v0.w, v1.x, v1.y, v1.z, v1.w};
#pragma unroll
                for (int j = 0; j < 8; j++) {
                    oacc[0][j] += p0 * vv[j];
                    oacc[1][j] += p1 * vv[j];
                    oacc[2][j] += p2 * vv[j];
                    oacc[3][j] += p3 * vv[j];
                }
            }
        }
        __syncthreads();

#pragma unroll
        for (int i = 0; i < 4; i++)
#pragma unroll
            for (int j = 0; j < 8; j++)
                sm[OFF_S + grp * 2176 + (tyq4 + i) * 68 + txd8 + j] = oacc[i][j];
        __syncthreads();

#pragma unroll
        for (int e = 0; e < 8; e++) {
            int idx = tid + e * 256;
            int q = idx >> 6, d = idx & 63;
            float s = sm[OFF_S + 0 * 2176 + q * 68 + d]
                    + sm[OFF_S + 1 * 2176 + q * 68 + d]
                    + sm[OFF_S + 2 * 2176 + q * 68 + d]
                    + sm[OFF_S + 3 * 2176 + q * 68 + d];
            g_O[((size_t)(b * NT + q0 + q)) * NDM + h * 64 + d] = s * sm[OFF_R + q];
        }
    }
}

__global__ void finalize_cov_kernel(const float* __restrict__ coverage,
                                    float* __restrict__ outcov)
{
    int i = blockIdx.x * 256 + threadIdx.x;
    if (i < NB * NT) outcov[i] = coverage[i] + g_covacc[i] * (1.0f / NH);
}

// ================= launcher =================
extern "C" void kernel_launch(void* const* d_in, const int* in_sizes, int n_in,
                              void* d_out, int out_size)
{
    const float* query    = (const float*)d_in[0];
    const float* memory   = (const float*)d_in[1];
    const float* coverage = (const float*)d_in[2];
    const float* Wq       = (const float*)d_in[3];
    const float* bq       = (const float*)d_in[4];
    const float* Wk       = (const float*)d_in[5];
    const float* bk       = (const float*)d_in[6];
    const float* Wv       = (const float*)d_in[7];
    const float* bv       = (const float*)d_in[8];
    const float* Wo       = (const float*)d_in[9];
    const float* bo       = (const float*)d_in[10];
    const float* Wcov     = (const float*)d_in[11];
    float* out = (float*)d_out;

    cudaFuncSetAttribute(attn_kernel, cudaFuncAttributeMaxDynamicSharedMemorySize, A_SMEM_BYTES);

    zero_covacc_kernel<<<32, 256>>>();

    dim3 gg(NDM / 128, (NB * NT) / 128);   // (8, 64)
    gemm_mma<0><<<gg, 256>>>(query,  Wq, bq, nullptr);
    gemm_mma<1><<<gg, 256>>>(memory, Wk, bk, nullptr);
    gemm_mma<2><<<gg, 256>>>(memory, Wv, bv, nullptr);

    attn_kernel<<<dim3(NT / 32, NB * NH), 256, A_SMEM_BYTES>>>(coverage, Wcov);

    gemm_mma<3><<<gg, 256>>>(nullptr, Wo, bo, out);

    finalize_cov_kernel<<<32, 256>>>(coverage, out + (size_t)NB * NT * NDM);
}

// round 6
// speedup vs baseline: 3.7607x; 2.7160x over previous
#include <cuda_runtime.h>
#include <cstdint>

// CoverageAttention GB300 — R4: tf32 mma.sync everywhere + cp.async pipelines.
// B=8, Tq=Tk=1024, d_model=1024, H=16, hd=64, SCALE=8.

#define NB   8
#define NH   16
#define NT   1024
#define NDM  1024
#define NHD  64

__device__ float g_Q[NB * NH * NT * NHD];
__device__ float g_K[NB * NH * NT * NHD];
__device__ float g_V[NB * NH * NT * NHD];
__device__ float g_O[NB * NT * NDM];
__device__ float g_covacc[NB * NT];

__global__ void zero_covacc_kernel() {
    int i = blockIdx.x * 256 + threadIdx.x;
    if (i < NB * NT) g_covacc[i] = 0.0f;
}

__device__ __forceinline__ uint32_t smem_u32(const void* p) {
    uint32_t a;
    asm("{ .reg .u64 t; cvta.to.shared.u64 t, %1; cvt.u32.u64 %0, t; }" : "=r"(a) : "l"(p));
    return a;
}
__device__ __forceinline__ uint32_t f2tf32(float x) {
    uint32_t r;
    asm("cvt.rna.tf32.f32 %0, %1;" : "=r"(r) : "f"(x));
    return r;
}
__device__ __forceinline__ void mma_tf32(float c[4],
                                         uint32_t a0, uint32_t a1, uint32_t a2, uint32_t a3,
                                         uint32_t b0, uint32_t b1) {
    asm volatile(
        "mma.sync.aligned.m16n8k8.row.col.f32.tf32.tf32.f32 "
        "{%0,%1,%2,%3}, {%4,%5,%6,%7}, {%8,%9}, {%0,%1,%2,%3};"
        : "+f"(c[0]), "+f"(c[1]), "+f"(c[2]), "+f"(c[3])
        : "r"(a0), "r"(a1), "r"(a2), "r"(a3), "r"(b0), "r"(b1));
}

#define CP16(dst, src) \
    asm volatile("cp.async.cg.shared.global [%0], [%1], 16;" :: "r"(dst), "l"(src) : "memory")
#define CPC() asm volatile("cp.async.commit_group;" ::: "memory")
#define CPW(n) asm volatile("cp.async.wait_group %0;" :: "n"(n) : "memory")

// ================= tf32 GEMM (double-buffered) =================
// C[m,n] = A[m,:]·W[n,:] + bias[n]; M=8192, N=1024, K=1024.
// CTA 128x128, BK=16, 256 thr = 8 warps (2x4), warp 64x32 = 4x4 m16n8k8.
template <int DST>
__global__ __launch_bounds__(256, 2) void gemm_mma(
    const float* __restrict__ A, const float* __restrict__ W,
    const float* __restrict__ bias, float* __restrict__ Cout)
{
    __shared__ uint32_t As[2][128][20];
    __shared__ uint32_t Ws[2][128][20];

    int tid = threadIdx.x;
    int lane = tid & 31;
    int wid = tid >> 5;
    int warp_m = wid & 1;
    int warp_n = wid >> 1;
    int g = lane >> 2;
    int t = lane & 3;

    int bm = blockIdx.y * 128;
    int bn = blockIdx.x * 128;

    const float* Ap = (DST == 3) ? (const float*)g_O : A;

    int lr = tid >> 1;
    int kc = (tid & 1) * 8;
    const float* aP = Ap + (size_t)(bm + lr) * NDM + kc;
    const float* wP = W  + (size_t)(bn + lr) * NDM + kc;

    float c[4][4][4];
#pragma unroll
    for (int mi = 0; mi < 4; mi++)
#pragma unroll
        for (int ni = 0; ni < 4; ni++)
#pragma unroll
            for (int e = 0; e < 4; e++) c[mi][ni][e] = 0.0f;

    float4 ar0 = *(const float4*)(aP + 0);
    float4 ar1 = *(const float4*)(aP + 4);
    float4 wr0 = *(const float4*)(wP + 0);
    float4 wr1 = *(const float4*)(wP + 4);

    // store slab 0 into buf 0
    {
        uint4 q0 = {f2tf32(ar0.x), f2tf32(ar0.y), f2tf32(ar0.z), f2tf32(ar0.w)};
        uint4 q1 = {f2tf32(ar1.x), f2tf32(ar1.y), f2tf32(ar1.z), f2tf32(ar1.w)};
        *(uint4*)&As[0][lr][kc]     = q0;
        *(uint4*)&As[0][lr][kc + 4] = q1;
        uint4 p0 = {f2tf32(wr0.x), f2tf32(wr0.y), f2tf32(wr0.z), f2tf32(wr0.w)};
        uint4 p1 = {f2tf32(wr1.x), f2tf32(wr1.y), f2tf32(wr1.z), f2tf32(wr1.w)};
        *(uint4*)&Ws[0][lr][kc]     = p0;
        *(uint4*)&Ws[0][lr][kc + 4] = p1;
    }
    __syncthreads();

    for (int kt = 0; kt < 64; kt++) {
        int cur = kt & 1;
        if (kt < 63) {
            const float* aN = aP + (kt + 1) * 16;
            const float* wN = wP + (kt + 1) * 16;
            ar0 = *(const float4*)(aN + 0);
            ar1 = *(const float4*)(aN + 4);
            wr0 = *(const float4*)(wN + 0);
            wr1 = *(const float4*)(wN + 4);
        }

#pragma unroll
        for (int kk = 0; kk < 16; kk += 8) {
            uint32_t af[4][4];
#pragma unroll
            for (int mi = 0; mi < 4; mi++) {
                int r0 = warp_m * 64 + mi * 16 + g;
                af[mi][0] = As[cur][r0][kk + t];
                af[mi][1] = As[cur][r0 + 8][kk + t];
                af[mi][2] = As[cur][r0][kk + t + 4];
                af[mi][3] = As[cur][r0 + 8][kk + t + 4];
            }
            uint32_t bf[4][2];
#pragma unroll
            for (int ni = 0; ni < 4; ni++) {
                int c0 = warp_n * 32 + ni * 8 + g;
                bf[ni][0] = Ws[cur][c0][kk + t];
                bf[ni][1] = Ws[cur][c0][kk + t + 4];
            }
#pragma unroll
            for (int mi = 0; mi < 4; mi++)
#pragma unroll
                for (int ni = 0; ni < 4; ni++)
                    mma_tf32(c[mi][ni], af[mi][0], af[mi][1], af[mi][2], af[mi][3],
                             bf[ni][0], bf[ni][1]);
        }

        if (kt < 63) {
            int nxt = cur ^ 1;
            uint4 q0 = {f2tf32(ar0.x), f2tf32(ar0.y), f2tf32(ar0.z), f2tf32(ar0.w)};
            uint4 q1 = {f2tf32(ar1.x), f2tf32(ar1.y), f2tf32(ar1.z), f2tf32(ar1.w)};
            *(uint4*)&As[nxt][lr][kc]     = q0;
            *(uint4*)&As[nxt][lr][kc + 4] = q1;
            uint4 p0 = {f2tf32(wr0.x), f2tf32(wr0.y), f2tf32(wr0.z), f2tf32(wr0.w)};
            uint4 p1 = {f2tf32(wr1.x), f2tf32(wr1.y), f2tf32(wr1.z), f2tf32(wr1.w)};
            *(uint4*)&Ws[nxt][lr][kc]     = p0;
            *(uint4*)&Ws[nxt][lr][kc + 4] = p1;
            __syncthreads();
        }
    }

    // epilogue
#pragma unroll
    for (int mi = 0; mi < 4; mi++) {
#pragma unroll
        for (int ni = 0; ni < 4; ni++) {
            int n0 = bn + warp_n * 32 + ni * 8 + t * 2;
            float b0v = __ldg(bias + n0);
            float b1v = __ldg(bias + n0 + 1);
#pragma unroll
            for (int rh = 0; rh < 2; rh++) {
                int m = bm + warp_m * 64 + mi * 16 + g + rh * 8;
                float v0 = c[mi][ni][rh * 2 + 0] + b0v;
                float v1 = c[mi][ni][rh * 2 + 1] + b1v;
                int bb = m >> 10, tok = m & 1023;
                if (DST == 3) {
                    Cout[(size_t)m * NDM + n0] = v0;
                    Cout[(size_t)m * NDM + n0 + 1] = v1;
                } else {
                    size_t base = (((size_t)(bb * NH + (n0 >> 6))) * NT + tok) * NHD + (n0 & 63);
                    float* dst = (DST == 0) ? g_Q : (DST == 1) ? g_K : g_V;
                    dst[base] = v0; dst[base + 1] = v1;
                }
            }
        }
    }
}

// ================= attention (mma.sync) =================
// One CTA = (b,h) x 32 q rows. 256 threads / 8 warps. Exact fp32 softmax.
#define SROW    1033
#define OFF_S   0                    // 32 x 1033
#define OFF_KV0 33056                // 128 x 68 (buffer 0)
#define OFF_KV1 41760                // 128 x 68 (buffer 1)
#define OFF_QS  50464                // 32 x 68 raw Q staging
#define OFF_C   52640                // 1024 coverage bias
#define OFF_R   53664                // 32 reciprocals
#define A_SMEM_FLOATS 53696
#define A_SMEM_BYTES  (A_SMEM_FLOATS * 4)   // 214784

__global__ __launch_bounds__(256) void attn_mma(
    const float* __restrict__ coverage, const float* __restrict__ Wcov)
{
    extern __shared__ float sm[];
    uint32_t sb = smem_u32(sm);
    int tid = threadIdx.x;
    int lane = tid & 31, wid = tid >> 5;
    int g = lane >> 2, t = lane & 3;
    int bh = blockIdx.y, b = bh >> 4, h = bh & 15;
    int q0 = blockIdx.x * 32;
    float wcov = Wcov[h];

    const float* Qb = g_Q + (size_t)bh * NT * NHD + (size_t)q0 * NHD;
    const float* Kb = g_K + (size_t)bh * NT * NHD;
    const float* Vb = g_V + (size_t)bh * NT * NHD;

    // ---- prologue: Q + cov + K0 (group), K1 (group) ----
#pragma unroll
    for (int i = 0; i < 2; i++) {
        int id = tid + 256 * i;
        int q = id >> 4, c4 = id & 15;
        CP16(sb + (OFF_QS + q * 68 + c4 * 4) * 4, Qb + q * 64 + c4 * 4);
    }
    CP16(sb + (OFF_C + tid * 4) * 4, coverage + b * NT + tid * 4);
#pragma unroll
    for (int i = 0; i < 8; i++) {
        int id = tid + 256 * i;
        int tok = id >> 4, c4 = id & 15;
        CP16(sb + (OFF_KV0 + tok * 68 + c4 * 4) * 4, Kb + tok * 64 + c4 * 4);
    }
    CPC();
#pragma unroll
    for (int i = 0; i < 8; i++) {
        int id = tid + 256 * i;
        int tok = id >> 4, c4 = id & 15;
        CP16(sb + (OFF_KV1 + tok * 68 + c4 * 4) * 4, Kb + (128 + tok) * 64 + c4 * 4);
    }
    CPC();
    CPW(1);
    __syncthreads();

    // scale cov by wcov in-place (was raw coverage)
    for (int i = tid; i < NT; i += 256) sm[OFF_C + i] *= wcov;

    // build Q tf32 fragments (held in registers for all of phase 1)
    uint32_t qf[2][8][4];
#pragma unroll
    for (int mi = 0; mi < 2; mi++)
#pragma unroll
        for (int kk = 0; kk < 8; kk++) {
            int base = OFF_QS + (mi * 16 + g) * 68 + kk * 8 + t;
            qf[mi][kk][0] = f2tf32(sm[base]);
            qf[mi][kk][1] = f2tf32(sm[base + 8 * 68]);
            qf[mi][kk][2] = f2tf32(sm[base + 4]);
            qf[mi][kk][3] = f2tf32(sm[base + 8 * 68 + 4]);
        }
    __syncthreads();   // cov scaling complete before S writes read it

    // -------- phase 1: S = QK^T/8 + cov --------
    int tokb = wid * 16;
    for (int kt = 0; kt < 8; kt++) {
        if (kt) {
            if (kt < 7) { CPW(1); } else { CPW(0); }
            __syncthreads();
        }
        const float* Ks = sm + ((kt & 1) ? OFF_KV1 : OFF_KV0);
#pragma unroll
        for (int nj = 0; nj < 2; nj++) {
            float s0[4] = {0, 0, 0, 0}, s1[4] = {0, 0, 0, 0};
            const float* kr = Ks + (tokb + nj * 8 + g) * 68 + t;
#pragma unroll
            for (int kk = 0; kk < 8; kk++) {
                uint32_t b0 = f2tf32(kr[kk * 8]);
                uint32_t b1 = f2tf32(kr[kk * 8 + 4]);
                mma_tf32(s0, qf[0][kk][0], qf[0][kk][1], qf[0][kk][2], qf[0][kk][3], b0, b1);
                mma_tf32(s1, qf[1][kk][0], qf[1][kk][1], qf[1][kk][2], qf[1][kk][3], b0, b1);
            }
            int kgl = kt * 128 + tokb + nj * 8 + 2 * t;
            float cv0 = sm[OFF_C + kgl], cv1 = sm[OFF_C + kgl + 1];
            sm[OFF_S + g * SROW + kgl]            = s0[0] * 0.125f + cv0;
            sm[OFF_S + g * SROW + kgl + 1]        = s0[1] * 0.125f + cv1;
            sm[OFF_S + (g + 8) * SROW + kgl]      = s0[2] * 0.125f + cv0;
            sm[OFF_S + (g + 8) * SROW + kgl + 1]  = s0[3] * 0.125f + cv1;
            sm[OFF_S + (g + 16) * SROW + kgl]     = s1[0] * 0.125f + cv0;
            sm[OFF_S + (g + 16) * SROW + kgl + 1] = s1[1] * 0.125f + cv1;
            sm[OFF_S + (g + 24) * SROW + kgl]     = s1[2] * 0.125f + cv0;
            sm[OFF_S + (g + 24) * SROW + kgl + 1] = s1[3] * 0.125f + cv1;
        }
        __syncthreads();
        if (kt < 6) {
            uint32_t dof = (kt & 1) ? OFF_KV1 : OFF_KV0;
#pragma unroll
            for (int i = 0; i < 8; i++) {
                int id = tid + 256 * i;
                int tok = id >> 4, c4 = id & 15;
                CP16(sb + (dof + tok * 68 + c4 * 4) * 4,
                     Kb + ((kt + 2) * 128 + tok) * 64 + c4 * 4);
            }
            CPC();
        }
    }

    // issue V tiles 0 and 1 (hidden under softmax)
#pragma unroll
    for (int i = 0; i < 8; i++) {
        int id = tid + 256 * i;
        int tok = id >> 4, c4 = id & 15;
        CP16(sb + (OFF_KV0 + tok * 68 + c4 * 4) * 4, Vb + tok * 64 + c4 * 4);
    }
    CPC();
#pragma unroll
    for (int i = 0; i < 8; i++) {
        int id = tid + 256 * i;
        int tok = id >> 4, c4 = id & 15;
        CP16(sb + (OFF_KV1 + tok * 68 + c4 * 4) * 4, Vb + (128 + tok) * 64 + c4 * 4);
    }
    CPC();

    // -------- phase 2: softmax --------
    for (int q = wid; q < 32; q += 8) {
        float* row = &sm[OFF_S + q * SROW];
        float m = -1e30f;
        for (int k = lane; k < NT; k += 32) m = fmaxf(m, row[k]);
#pragma unroll
        for (int o = 16; o > 0; o >>= 1) m = fmaxf(m, __shfl_xor_sync(0xffffffff, m, o));
        float l = 0.0f;
        for (int k = lane; k < NT; k += 32) {
            float e = __expf(row[k] - m);
            row[k] = e;
            l += e;
        }
#pragma unroll
        for (int o = 16; o > 0; o >>= 1) l += __shfl_xor_sync(0xffffffff, l, o);
        if (lane == 0) sm[OFF_R + q] = 1.0f / l;
    }
    __syncthreads();

    // -------- phase 3: coverage column sums --------
    for (int k = tid; k < NT; k += 256) {
        float s = 0.0f;
#pragma unroll 8
        for (int q = 0; q < 32; q++)
            s += sm[OFF_S + q * SROW + k] * sm[OFF_R + q];
        atomicAdd(&g_covacc[b * NT + k], s);
    }

    // -------- phase 4: O = P @ V --------
    int mh = wid & 1, nh = (wid >> 1) & 1, kp = wid >> 2;
    float oa[4][4];
#pragma unroll
    for (int nj = 0; nj < 4; nj++)
#pragma unroll
        for (int e = 0; e < 4; e++) oa[nj][e] = 0.0f;

    for (int kt = 0; kt < 8; kt++) {
        if (kt < 7) { CPW(1); } else { CPW(0); }
        __syncthreads();
        const float* Vs = sm + ((kt & 1) ? OFF_KV1 : OFF_KV0);
#pragma unroll
        for (int ks8 = 0; ks8 < 8; ks8++) {
            int kb = (ks8 * 2 + kp) * 8;
            int ar = OFF_S + (mh * 16 + g) * SROW + kt * 128 + kb + t;
            uint32_t a0 = f2tf32(sm[ar]);
            uint32_t a1 = f2tf32(sm[ar + 8 * SROW]);
            uint32_t a2 = f2tf32(sm[ar + 4]);
            uint32_t a3 = f2tf32(sm[ar + 8 * SROW + 4]);
#pragma unroll
            for (int nj = 0; nj < 4; nj++) {
                int d0 = nh * 32 + nj * 8 + g;
                uint32_t b0 = f2tf32(Vs[(kb + t) * 68 + d0]);
                uint32_t b1 = f2tf32(Vs[(kb + t + 4) * 68 + d0]);
                mma_tf32(oa[nj], a0, a1, a2, a3, b0, b1);
            }
        }
        __syncthreads();
        if (kt < 6) {
            uint32_t dof = (kt & 1) ? OFF_KV1 : OFF_KV0;
#pragma unroll
            for (int i = 0; i < 8; i++) {
                int id = tid + 256 * i;
                int tok = id >> 4, c4 = id & 15;
                CP16(sb + (dof + tok * 68 + c4 * 4) * 4,
                     Vb + ((kt + 2) * 128 + tok) * 64 + c4 * 4);
            }
            CPC();
        }
    }

    // partial reduction across kp via smem
    {
        float* op = sm + OFF_KV0 + kp * 2176;
        int rb = mh * 16 + g;
#pragma unroll
        for (int nj = 0; nj < 4; nj++) {
            int col = nh * 32 + nj * 8 + 2 * t;
            op[rb * 68 + col]           = oa[nj][0];
            op[rb * 68 + col + 1]       = oa[nj][1];
            op[(rb + 8) * 68 + col]     = oa[nj][2];
            op[(rb + 8) * 68 + col + 1] = oa[nj][3];
        }
    }
    __syncthreads();
#pragma unroll
    for (int e = 0; e < 8; e++) {
        int idx = tid + e * 256;
        int q = idx >> 6, d = idx & 63;
        float val = (sm[OFF_KV0 + q * 68 + d] + sm[OFF_KV0 + 2176 + q * 68 + d])
                    * sm[OFF_R + q];
        g_O[((size_t)(b * NT + q0 + q)) * NDM + h * 64 + d] = val;
    }
}

__global__ void finalize_cov_kernel(const float* __restrict__ coverage,
                                    float* __restrict__ outcov)
{
    int i = blockIdx.x * 256 + threadIdx.x;
    if (i < NB * NT) outcov[i] = coverage[i] + g_covacc[i] * (1.0f / NH);
}

// ================= launcher =================
extern "C" void kernel_launch(void* const* d_in, const int* in_sizes, int n_in,
                              void* d_out, int out_size)
{
    const float* query    = (const float*)d_in[0];
    const float* memory   = (const float*)d_in[1];
    const float* coverage = (const float*)d_in[2];
    const float* Wq       = (const float*)d_in[3];
    const float* bq       = (const float*)d_in[4];
    const float* Wk       = (const float*)d_in[5];
    const float* bk       = (const float*)d_in[6];
    const float* Wv       = (const float*)d_in[7];
    const float* bv       = (const float*)d_in[8];
    const float* Wo       = (const float*)d_in[9];
    const float* bo       = (const float*)d_in[10];
    const float* Wcov     = (const float*)d_in[11];
    float* out = (float*)d_out;

    cudaFuncSetAttribute(attn_mma, cudaFuncAttributeMaxDynamicSharedMemorySize, A_SMEM_BYTES);

    zero_covacc_kernel<<<32, 256>>>();

    dim3 gg(NDM / 128, (NB * NT) / 128);   // (8, 64)
    gemm_mma<0><<<gg, 256>>>(query,  Wq, bq, nullptr);
    gemm_mma<1><<<gg, 256>>>(memory, Wk, bk, nullptr);
    gemm_mma<2><<<gg, 256>>>(memory, Wv, bv, nullptr);

    attn_mma<<<dim3(NT / 32, NB * NH), 256, A_SMEM_BYTES>>>(coverage, Wcov);

    gemm_mma<3><<<gg, 256>>>(nullptr, Wo, bo, out);

    finalize_cov_kernel<<<32, 256>>>(coverage, out + (size_t)NB * NT * NDM);
}